// round 17
// baseline (speedup 1.0000x reference)
#include <cuda_runtime.h>
#include <cuda_fp16.h>
#include <cstdint>
#include <cstddef>

// ---------------- problem constants ----------------
#define M_TOK 8192
#define IN_F  4096
#define OUT_F 4096
#define RANK  32
#define GS    64
#define KT8   (IN_F / 64)    // 64 k-tiles of 64 (one scale group each)

// ---------------- scratch (device globals; no runtime allocation) ----------------
__device__ __align__(128) int8_t g_Aq   [(size_t)M_TOK * IN_F];   // activation int4 codes
__device__ __align__(128) int8_t g_Bq   [(size_t)OUT_F * IN_F];   // weight int4 codes
__device__ __align__(128) float  g_as   [(size_t)GS * M_TOK];     // [g][m] activation scales
__device__ __align__(128) __half g_Xs   [(size_t)M_TOK * IN_F];   // smoothed activations (half)
__device__ __align__(128) __half g_Alora[(size_t)M_TOK * RANK];   // lora_act (half)
__device__ __align__(128) __half g_Bpu  [(size_t)OUT_F * RANK];   // proj_up (half)

// ---------------- common helpers ----------------
__device__ __forceinline__ uint32_t smem_u32(const void* p) {
    uint32_t a;
    asm("{ .reg .u64 t; cvta.to.shared.u64 t, %1; cvt.u32.u64 %0, t; }" : "=r"(a) : "l"(p));
    return a;
}
__device__ __forceinline__ void cp16s(uint32_t sdst, const void* gsrc) {
    asm volatile("cp.async.cg.shared.global [%0], [%1], 16;\n" :: "r"(sdst), "l"(gsrc));
}
#define LDSM_X4(r0, r1, r2, r3, a)                                             \
    asm volatile("ldmatrix.sync.aligned.m8n8.x4.shared.b16 {%0,%1,%2,%3}, [%4];" \
                 : "=r"(r0), "=r"(r1), "=r"(r2), "=r"(r3) : "r"(a))
#define MMA_16816(C, A0, A1, A2, A3, B0, B1)                                   \
    asm volatile("mma.sync.aligned.m16n8k16.row.col.f32.f16.f16.f32 "          \
                 "{%0,%1,%2,%3}, {%4,%5,%6,%7}, {%8,%9}, {%0,%1,%2,%3};\n"     \
                 : "+f"((C)[0]), "+f"((C)[1]), "+f"((C)[2]), "+f"((C)[3])      \
                 : "r"(A0), "r"(A1), "r"(A2), "r"(A3), "r"(B0), "r"(B1))
#define MMA_S8_Z(S, A0, A1, A2, A3, B0, B1)                                    \
    asm volatile("mma.sync.aligned.m16n8k32.row.col.s32.s8.s8.s32 "            \
                 "{%0,%1,%2,%3}, {%4,%5,%6,%7}, {%8,%9}, {%10,%10,%10,%10};\n" \
                 : "=r"((S)[0]), "=r"((S)[1]), "=r"((S)[2]), "=r"((S)[3])      \
                 : "r"(A0), "r"(A1), "r"(A2), "r"(A3), "r"(B0), "r"(B1), "r"(0))
#define MMA_S8_A(S, A0, A1, A2, A3, B0, B1)                                    \
    asm volatile("mma.sync.aligned.m16n8k32.row.col.s32.s8.s8.s32 "            \
                 "{%0,%1,%2,%3}, {%4,%5,%6,%7}, {%8,%9}, {%0,%1,%2,%3};\n"     \
                 : "+r"((S)[0]), "+r"((S)[1]), "+r"((S)[2]), "+r"((S)[3])      \
                 : "r"(A0), "r"(A1), "r"(A2), "r"(A3), "r"(B0), "r"(B1))

// =======================================================================
// Kernel 1: activation prep.
// =======================================================================
__global__ void __launch_bounds__(256) prep_x_kernel(const float* __restrict__ x,
                                                     const float* __restrict__ smooth) {
    const int m = blockIdx.x;
    const int t = threadIdx.x;
    const int i0 = t * 16;

    float v[16];
    const float4* xp = (const float4*)(x + (size_t)m * IN_F + i0);
    const float4* sp = (const float4*)(smooth + i0);
#pragma unroll
    for (int j = 0; j < 4; ++j) {
        float4 xv = xp[j];
        float4 sv = sp[j];
        v[4*j+0] = xv.x / sv.x;
        v[4*j+1] = xv.y / sv.y;
        v[4*j+2] = xv.z / sv.z;
        v[4*j+3] = xv.w / sv.w;
    }

    __align__(16) __half hs[16];
#pragma unroll
    for (int j = 0; j < 16; ++j) hs[j] = __float2half_rn(v[j]);
    {
        uint4* dst = (uint4*)(g_Xs + (size_t)m * IN_F + i0);
        dst[0] = ((const uint4*)hs)[0];
        dst[1] = ((const uint4*)hs)[1];
    }

    float am = 0.f;
#pragma unroll
    for (int j = 0; j < 16; ++j) am = fmaxf(am, fabsf(v[j]));
    am = fmaxf(am, __shfl_xor_sync(0xffffffffu, am, 1));
    am = fmaxf(am, __shfl_xor_sync(0xffffffffu, am, 2));
    const float asc = fmaxf(am / 7.0f, 1e-8f);

    __align__(16) int8_t qb[16];
#pragma unroll
    for (int j = 0; j < 16; ++j) {
        float q = rintf(v[j] / asc);            // round-half-even == jnp.round
        q = fminf(fmaxf(q, -8.0f), 7.0f);
        qb[j] = (int8_t)(int)q;
    }
    *(uint4*)(g_Aq + (size_t)m * IN_F + i0) = *(const uint4*)qb;

    if ((t & 3) == 0) g_as[(size_t)(t >> 2) * M_TOK + m] = asc;   // group = i0/64
}

// =======================================================================
// Kernel 2: weight prep (int32-promoted or raw int8 qweight -> g_Bq; pu -> half)
// =======================================================================
__global__ void __launch_bounds__(256) prep_w_kernel(const void* __restrict__ qw_raw,
                                                     const float* __restrict__ pu) {
    const int o = blockIdx.x;
    const int t = threadIdx.x;
    const int i0 = t * 16;

    int is_i32 = 1;
    {
        const int* qd = (const int*)qw_raw;
        for (int i = 0; i < 64; ++i) {
            int vq = qd[i];
            if (vq < -8 || vq > 7) { is_i32 = 0; break; }
        }
    }

    __align__(16) int8_t qb[16];
    if (is_i32) {
        const int4* qp = (const int4*)((const int*)qw_raw + (size_t)o * IN_F + i0);
#pragma unroll
        for (int j = 0; j < 4; ++j) {
            int4 w = qp[j];
            qb[4*j+0] = (int8_t)w.x;
            qb[4*j+1] = (int8_t)w.y;
            qb[4*j+2] = (int8_t)w.z;
            qb[4*j+3] = (int8_t)w.w;
        }
    } else {
        *(uint4*)qb = *(const uint4*)((const int8_t*)qw_raw + (size_t)o * IN_F + i0);
    }
    *(uint4*)(g_Bq + (size_t)o * IN_F + i0) = *(const uint4*)qb;

    if (t < RANK)
        g_Bpu[(size_t)o * RANK + t] = __float2half_rn(pu[(size_t)o * RANK + t]);
}

// =======================================================================
// Kernel 3: lora_down via mma.sync -> g_Alora [M][32] (half)
// =======================================================================
#define LSA 72
#define L_XS_ROWS 128
#define L_PD_OFF  128
#define L_STAGE_H ((L_XS_ROWS + RANK) * LSA)
#define L_SMEM_BYTES (3 * L_STAGE_H * 2)       // 69120 bytes
#define L_KC (IN_F / 64)

__device__ __forceinline__ void lora_load_stage(uint32_t sbase, int slot, int kc,
                                                int m0, const float* __restrict__ pd,
                                                int t) {
    uint32_t st = sbase + slot * (L_STAGE_H * 2);
    const __half* gX = g_Xs + (size_t)m0 * IN_F + kc * 64;
#pragma unroll
    for (int j = 0; j < 4; ++j) {
        int c = j * 256 + t;
        int row = c >> 3, cc = c & 7;
        cp16s(st + (row * LSA + cc * 8) * 2, gX + (size_t)row * IN_F + cc * 8);
    }
    int k = t >> 2;
    int rg = (t & 3) * 8;
    const float* prow = pd + (size_t)(kc * 64 + k) * RANK + rg;
    float4 p0 = *(const float4*)(prow);
    float4 p1 = *(const float4*)(prow + 4);
    __half hv[8];
    hv[0] = __float2half_rn(p0.x); hv[1] = __float2half_rn(p0.y);
    hv[2] = __float2half_rn(p0.z); hv[3] = __float2half_rn(p0.w);
    hv[4] = __float2half_rn(p1.x); hv[5] = __float2half_rn(p1.y);
    hv[6] = __float2half_rn(p1.z); hv[7] = __float2half_rn(p1.w);
#pragma unroll
    for (int i = 0; i < 8; ++i) {
        uint32_t addr = st + ((L_PD_OFF + rg + i) * LSA + k) * 2;
        asm volatile("st.shared.b16 [%0], %1;" :: "r"(addr),
                     "h"(*(const uint16_t*)&hv[i]) : "memory");
    }
}

__global__ void __launch_bounds__(256, 1) lora_down_kernel(const float* __restrict__ pd) {
    extern __shared__ __align__(128) __half lsmem[];
    uint32_t sbase = smem_u32(lsmem);

    const int t = threadIdx.x;
    const int wid = t >> 5, lane = t & 31;
    const int gid = lane >> 2, tid4 = lane & 3;
    const int m0 = blockIdx.x * L_XS_ROWS;

    const int a_r = (lane & 15);
    const int a_k = (lane >> 4) * 8;
    const int b_r = ((lane >> 4) << 3) + (lane & 7);
    const int b_k = ((lane >> 3) & 1) * 8;

    float c[4][4];
#pragma unroll
    for (int ni = 0; ni < 4; ++ni)
#pragma unroll
        for (int j = 0; j < 4; ++j) c[ni][j] = 0.f;

    lora_load_stage(sbase, 0, 0, m0, pd, t);
    asm volatile("cp.async.commit_group;\n");
    lora_load_stage(sbase, 1, 1, m0, pd, t);
    asm volatile("cp.async.commit_group;\n");

    int s = 0;
    for (int kc = 0; kc < L_KC; ++kc) {
        asm volatile("cp.async.wait_group 1;\n");
        __syncthreads();

        if (kc + 2 < L_KC) {
            int s2 = kc + 2;
            s2 -= (s2 / 3) * 3;
            lora_load_stage(sbase, s2, kc + 2, m0, pd, t);
        }
        asm volatile("cp.async.commit_group;\n");

        uint32_t st = sbase + s * (L_STAGE_H * 2);
#pragma unroll
        for (int ks = 0; ks < 4; ++ks) {
            uint32_t af[4], bf[4][2];
            {
                uint32_t addr = st + ((wid * 16 + a_r) * LSA + ks * 16 + a_k) * 2;
                LDSM_X4(af[0], af[1], af[2], af[3], addr);
            }
#pragma unroll
            for (int np = 0; np < 2; ++np) {
                uint32_t addr = st + ((L_PD_OFF + np * 16 + b_r) * LSA + ks * 16 + b_k) * 2;
                LDSM_X4(bf[2*np][0], bf[2*np][1], bf[2*np+1][0], bf[2*np+1][1], addr);
            }
#pragma unroll
            for (int ni = 0; ni < 4; ++ni)
                MMA_16816(c[ni], af[0], af[1], af[2], af[3], bf[ni][0], bf[ni][1]);
        }
        ++s;
        if (s == 3) s = 0;
    }

#pragma unroll
    for (int ni = 0; ni < 4; ++ni) {
        int row = m0 + wid * 16 + gid;
        int col = ni * 8 + tid4 * 2;
        __half2 v0 = __floats2half2_rn(c[ni][0], c[ni][1]);
        __half2 v1 = __floats2half2_rn(c[ni][2], c[ni][3]);
        *(__half2*)(g_Alora + (size_t)row * RANK + col) = v0;
        *(__half2*)(g_Alora + (size_t)(row + 8) * RANK + col) = v1;
    }
}

// =======================================================================
// Kernel 4: int8 main GEMM + per-group f32 rescale + f16 lora epilogue.
// BM=128, BN=64, BK=64. 128 threads = 4 warps (2x2 warp grid),
// warp tile 64x32: 4mi x 4ni. __launch_bounds__(128,4) -> 4 CTAs/SM:
// each SMSP runs 4 warps from 4 INDEPENDENT CTAs (no shared barriers).
// smem rows: 64B data + 16B pad (stride 80).
// =======================================================================
#define SB 80
#define S_B_OFF  (128 * SB)                    // 10240 (A: 128 rows)
#define S_AS_OFF (S_B_OFF + 64 * SB)           // 15360 (B: 64 rows)
#define S_WS_OFF (S_AS_OFF + 512)              // 15872 (as: 128 f32)
#define STAGE_B  (S_WS_OFF + 256)              // 16128 (ws: 64 f32)
#define G_SMEM   (3 * STAGE_B)                 // 48384 per CTA (x4 = 193.5KB)
#define G_THREADS 128

__device__ __forceinline__ void load_stage8(uint32_t sbase, int slot, int kt,
                                            int m0, int n0, int t,
                                            const float* __restrict__ wsc) {
    uint32_t st = sbase + slot * STAGE_B;
    const int8_t* gA = g_Aq + (size_t)m0 * IN_F + kt * 64;
    const int8_t* gB = g_Bq + (size_t)n0 * IN_F + kt * 64;
#pragma unroll
    for (int j = 0; j < 4; ++j) {              // A: 512 chunks of 16B
        int c = j * G_THREADS + t;
        int row = c >> 2, cc = c & 3;
        cp16s(st + row * SB + cc * 16, gA + (size_t)row * IN_F + cc * 16);
    }
#pragma unroll
    for (int j = 0; j < 2; ++j) {              // B: 256 chunks
        int c = j * G_THREADS + t;
        int row = c >> 2, cc = c & 3;
        cp16s(st + S_B_OFF + row * SB + cc * 16, gB + (size_t)row * IN_F + cc * 16);
    }
    if (t < 32) {                              // as: 128 f32 = 32 chunks
        cp16s(st + S_AS_OFF + t * 16, g_as + (size_t)kt * M_TOK + m0 + t * 4);
    } else if (t < 48) {                       // ws: 64 f32 = 16 chunks
        int idx = t - 32;
        cp16s(st + S_WS_OFF + idx * 16, wsc + (size_t)kt * OUT_F + n0 + idx * 4);
    }
}

__global__ void __launch_bounds__(G_THREADS, 4) gemm_int8_kernel(
        float* __restrict__ out, const float* __restrict__ wsc) {
    extern __shared__ __align__(128) char gsm[];
    uint32_t sbase = smem_u32(gsm);

    const int t = threadIdx.x;
    const int wid = t >> 5, lane = t & 31;
    const int wm = wid >> 1, wn = wid & 1;        // 2 x 2 warp grid
    const int gid = lane >> 2, tid4 = lane & 3;
    const int n0 = blockIdx.x * 64;
    const int m0 = blockIdx.y * 128;

    const int a_r  = (lane & 15);
    const int a_c  = (lane >> 4) * 16;
    const int b_r  = ((lane >> 4) << 3) + (lane & 7);
    const int b_c  = ((lane >> 3) & 1) * 16;

    float c[4][4][4];
#pragma unroll
    for (int mi = 0; mi < 4; ++mi)
#pragma unroll
        for (int ni = 0; ni < 4; ++ni)
#pragma unroll
            for (int j = 0; j < 4; ++j) c[mi][ni][j] = 0.f;

    load_stage8(sbase, 0, 0, m0, n0, t, wsc);
    asm volatile("cp.async.commit_group;\n");
    load_stage8(sbase, 1, 1, m0, n0, t, wsc);
    asm volatile("cp.async.commit_group;\n");

    int s = 0;
    for (int kt = 0; kt < KT8; ++kt) {
        asm volatile("cp.async.wait_group 1;\n");
        __syncthreads();

        if (kt + 2 < KT8) {
            int s2 = kt + 2;
            s2 -= (s2 / 3) * 3;
            load_stage8(sbase, s2, kt + 2, m0, n0, t, wsc);
        }
        asm volatile("cp.async.commit_group;\n");

        uint32_t aS = sbase + s * STAGE_B;
        uint32_t bS = aS + S_B_OFF;
        const float* asp = (const float*)(gsm + s * STAGE_B + S_AS_OFF);
        const float* wsp = (const float*)(gsm + s * STAGE_B + S_WS_OFF);

        float wse[4], wso[4];
#pragma unroll
        for (int ni = 0; ni < 4; ++ni) {
            int col = wn * 32 + ni * 8 + tid4 * 2;
            wse[ni] = wsp[col];
            wso[ni] = wsp[col + 1];
        }

        uint32_t bf0[4][2], bf1[4][2];
#pragma unroll
        for (int np = 0; np < 2; ++np) {
            uint32_t addr = bS + (wn * 32 + np * 16 + b_r) * SB + b_c;
            LDSM_X4(bf0[2*np][0], bf0[2*np][1], bf0[2*np+1][0], bf0[2*np+1][1], addr);
            LDSM_X4(bf1[2*np][0], bf1[2*np][1], bf1[2*np+1][0], bf1[2*np+1][1], addr + 32);
        }

#pragma unroll
        for (int mi = 0; mi < 4; ++mi) {
            uint32_t addr = aS + (wm * 64 + mi * 16 + a_r) * SB + a_c;
            uint32_t af0[4], af1[4];
            LDSM_X4(af0[0], af0[1], af0[2], af0[3], addr);
            LDSM_X4(af1[0], af1[1], af1[2], af1[3], addr + 32);
            float asl = asp[wm * 64 + mi * 16 + gid];
            float ash = asp[wm * 64 + mi * 16 + gid + 8];
#pragma unroll
            for (int ni = 0; ni < 4; ++ni) {
                int sacc[4];
                MMA_S8_Z(sacc, af0[0], af0[1], af0[2], af0[3], bf0[ni][0], bf0[ni][1]);
                MMA_S8_A(sacc, af1[0], af1[1], af1[2], af1[3], bf1[ni][0], bf1[ni][1]);
                c[mi][ni][0] += __int2float_rn(sacc[0]) * (asl * wse[ni]);
                c[mi][ni][1] += __int2float_rn(sacc[1]) * (asl * wso[ni]);
                c[mi][ni][2] += __int2float_rn(sacc[2]) * (ash * wse[ni]);
                c[mi][ni][3] += __int2float_rn(sacc[3]) * (ash * wso[ni]);
            }
        }
        ++s;
        if (s == 3) s = 0;
    }

    // ---- lora epilogue: c += lora_act(128x32) @ proj_up(64x32)^T  (f16 MMA)
    asm volatile("cp.async.wait_group 0;\n");
    __syncthreads();
    {
        uint32_t st = sbase;                      // reuse stage 0
#pragma unroll
        for (int j = 0; j < 4; ++j) {             // A-lora: 512 chunks (128 rows x 64B)
            int cth = j * G_THREADS + t;
            int row = cth >> 2, cc = cth & 3;
            cp16s(st + row * SB + cc * 16,
                  (const char*)g_Alora + (size_t)(m0 + row) * 64 + cc * 16);
        }
#pragma unroll
        for (int j = 0; j < 2; ++j) {             // B-pu: 256 chunks (64 rows x 64B)
            int cth = j * G_THREADS + t;
            int row = cth >> 2, cc = cth & 3;
            cp16s(st + S_B_OFF + row * SB + cc * 16,
                  (const char*)g_Bpu + (size_t)(n0 + row) * 64 + cc * 16);
        }
        asm volatile("cp.async.commit_group;\n");
        asm volatile("cp.async.wait_group 0;\n");
        __syncthreads();

#pragma unroll
        for (int ks = 0; ks < 2; ++ks) {          // k = 32 halfs = 2 x k16
            uint32_t bf[4][2];
#pragma unroll
            for (int np = 0; np < 2; ++np) {
                uint32_t addr = st + S_B_OFF + (wn * 32 + np * 16 + b_r) * SB + ks * 32 + b_c;
                LDSM_X4(bf[2*np][0], bf[2*np][1], bf[2*np+1][0], bf[2*np+1][1], addr);
            }
#pragma unroll
            for (int mi = 0; mi < 4; ++mi) {
                uint32_t addr = st + (wm * 64 + mi * 16 + a_r) * SB + ks * 32 + a_c;
                uint32_t af[4];
                LDSM_X4(af[0], af[1], af[2], af[3], addr);
#pragma unroll
                for (int ni = 0; ni < 4; ++ni)
                    MMA_16816(c[mi][ni], af[0], af[1], af[2], af[3],
                              bf[ni][0], bf[ni][1]);
            }
        }
    }

    // ---- store
#pragma unroll
    for (int mi = 0; mi < 4; ++mi) {
#pragma unroll
        for (int ni = 0; ni < 4; ++ni) {
            int row = m0 + wm * 64 + mi * 16 + gid;
            int col = n0 + wn * 32 + ni * 8 + tid4 * 2;
            *(float2*)(out + (size_t)row * OUT_F + col) =
                make_float2(c[mi][ni][0], c[mi][ni][1]);
            *(float2*)(out + (size_t)(row + 8) * OUT_F + col) =
                make_float2(c[mi][ni][2], c[mi][ni][3]);
        }
    }
}

// =======================================================================
// launch: prep_x, prep_w, lora_down, gemm (gemm = 4th launch -> ncu slot)
// =======================================================================
extern "C" void kernel_launch(void* const* d_in, const int* in_sizes, int n_in,
                              void* d_out, int out_size) {
    const void* x   = nullptr;
    const void* qw  = nullptr;
    const void* wsc = nullptr;
    const void* smo = nullptr;
    const void* pd  = nullptr;
    const void* pu  = nullptr;

    for (int i = 0; i < n_in; ++i) {
        switch (in_sizes[i]) {
            case 33554432: x   = d_in[i]; break;
            case 16777216: qw  = d_in[i]; break;
            case 262144:   wsc = d_in[i]; break;
            case 4096:     smo = d_in[i]; break;
            case 131072:   if (!pd) pd = d_in[i]; else pu = d_in[i]; break;
            default: break;
        }
    }
    if (!x || !qw || !wsc || !smo || !pd || !pu) {
        x   = d_in[0];
        qw  = d_in[1];
        wsc = d_in[2];
        smo = d_in[3];
        pd  = d_in[4];
        pu  = d_in[5];
    }

    float* out = (float*)d_out;

    cudaFuncSetAttribute(gemm_int8_kernel,
                         cudaFuncAttributeMaxDynamicSharedMemorySize, G_SMEM);
    cudaFuncSetAttribute(lora_down_kernel,
                         cudaFuncAttributeMaxDynamicSharedMemorySize, L_SMEM_BYTES);

    prep_x_kernel<<<M_TOK, 256>>>((const float*)x, (const float*)smo);
    prep_w_kernel<<<OUT_F, 256>>>(qw, (const float*)pu);
    lora_down_kernel<<<M_TOK / 128, 256, L_SMEM_BYTES>>>((const float*)pd);
    gemm_int8_kernel<<<dim3(OUT_F / 64, M_TOK / 128), G_THREADS, G_SMEM>>>(
        out, (const float*)wsc);
}